// round 4
// baseline (speedup 1.0000x reference)
#include <cuda_runtime.h>
#include <cuda_bf16.h>

// FQCNN_layer: closed-form evaluation.
//
// Math: expval(Z on wire 4) is invariant under the post-encoding circuit
// (H on wire 5, controlled-U3s on wire 6) since those are unitaries on wires
// != 4. After H^{x4} on wires 0-3 and the commuting (controlled-)RYs on wire 4:
//   <Z> = (1/16) * [ 8 cos(p0) + 2 cos(p0+p1) + 2 cos(p0+p2) + cos(p0+p3)
//                   + cos(p0+p1+p3) + cos(p0+p2+p3) + cos(p0+p1+p2+p3) ]
// with (p0,p1,p2,p3) = (im[j,k], im[j,k+1], im[j+1,k], im[j+1,k+1]).
// U3_w is provably unused.

#define BC_TOTAL   48        // 16 * 3
#define N_PAIRS    98304     // 16*3*64*64 / 2 (each thread -> 2 outputs)

__device__ __forceinline__ float patch_ev(float p0, float p1, float p2, float p3) {
    float s = 8.0f * __cosf(p0)
            + 2.0f * __cosf(p0 + p1)
            + 2.0f * __cosf(p0 + p2)
            +        __cosf(p0 + p3)
            +        __cosf(p0 + p1 + p3)
            +        __cosf(p0 + p2 + p3)
            +        __cosf(p0 + p1 + p2 + p3);
    return s * 0.0625f;
}

__global__ __launch_bounds__(256) void fqcnn_kernel(const float4* __restrict__ in4,
                                                    float2* __restrict__ out2) {
    int i = blockIdx.x * blockDim.x + threadIdx.x;
    if (i >= N_PAIRS) return;

    int ow2 = i & 31;          // which float4 (2 patches) along the row
    int oh  = (i >> 5) & 63;   // output row
    int bc  = i >> 11;         // batch*channel plane

    // input: [bc][128 rows][32 float4 per row]
    int base = (bc * 128 + 2 * oh) * 32 + ow2;
    const float4 r0 = in4[base];        // row 2*oh   : p0a p1a p0b p1b
    const float4 r1 = in4[base + 32];   // row 2*oh+1 : p2a p3a p2b p3b

    float2 o;
    o.x = patch_ev(r0.x, r0.y, r1.x, r1.y);
    o.y = patch_ev(r0.z, r0.w, r1.z, r1.w);

    // output: [bc][64 rows][32 float2 per row]
    out2[(bc * 64 + oh) * 32 + ow2] = o;
}

extern "C" void kernel_launch(void* const* d_in, const int* in_sizes, int n_in,
                              void* d_out, int out_size) {
    const float4* x   = (const float4*)d_in[0];   // [16,3,128,128] fp32
    // d_in[1] = U3_w — unused (see math above)
    float2* out = (float2*)d_out;                 // [16,3,64,64] fp32

    const int threads = 256;
    const int blocks  = (N_PAIRS + threads - 1) / threads;  // 384
    fqcnn_kernel<<<blocks, threads>>>(x, out);
}